// round 2
// baseline (speedup 1.0000x reference)
#include <cuda_runtime.h>
#include <cuda_bf16.h>

#define Hh 250
#define Ww 400
#define N_RAYS (Hh*Ww)            // 100000
#define N_SAMPLES 1000000
#define P_CNT 50000
#define C_CNT 16
#define DIMM 8
#define STEP_SIZE 0.005f
// per-p block of trivecs: C*3*DIM = 384 floats
#define PBLK 384

// Scratch (static device allocations are permitted)
__device__ float  g_trivecsT[(size_t)P_CNT * PBLK];   // (P, 3, DIM, C) layout, ~76.8MB
__device__ float4 g_samp[N_SAMPLES];                  // {alpha, r, g, b}
__device__ float  g_logt[N_SAMPLES];                  // log transmittance per sample

// ---------------------------------------------------------------------------
// Kernel 1: transpose trivecs (P,C,3,DIM) -> (P,3,DIM,C) so the 16-channel
// gather in the sample pass is a contiguous 64B chunk.
// ---------------------------------------------------------------------------
__global__ __launch_bounds__(128) void transpose_k(const float* __restrict__ in) {
    int p = blockIdx.x;
    __shared__ float sm[PBLK];
    const float* src = in + (size_t)p * PBLK;
    #pragma unroll
    for (int i = threadIdx.x; i < PBLK; i += 128) sm[i] = src[i];
    __syncthreads();
    float* dst = g_trivecsT + (size_t)p * PBLK;
    #pragma unroll
    for (int o = threadIdx.x; o < PBLK; o += 128) {
        int c = o & 15;
        int d = (o >> 4) & 7;
        int a = o >> 7;
        dst[o] = sm[c * 24 + a * 8 + d];
    }
}

// ---------------------------------------------------------------------------
// Kernel 2: per-sample feature/sigma/color. 4 threads per sample, 4 channels
// per thread via float4 loads; quad shuffle-reduce for sigma and rgb.
// ---------------------------------------------------------------------------
__global__ __launch_bounds__(256) void sample_k(
    const float* __restrict__ densities,   // (P, 16)
    const float* __restrict__ colors,      // (P, 16, 3)
    const float* __restrict__ gws,         // (N, 3)
    const float* __restrict__ gwl,         // (N, 3)
    const int*   __restrict__ gis,         // (N, 3)
    const int*   __restrict__ gil,         // (N, 3)
    const int*   __restrict__ tfid)        // (N,)
{
    int t = blockIdx.x * blockDim.x + threadIdx.x;
    int n = t >> 2;
    if (n >= N_SAMPLES) return;
    int q = t & 3;

    int p = tfid[n];
    const float* base = g_trivecsT + (size_t)p * PBLK + q * 4;

    float4 f = make_float4(1.f, 1.f, 1.f, 1.f);
    #pragma unroll
    for (int a = 0; a < 3; a++) {
        int   is = gis[n * 3 + a];
        int   il = gil[n * 3 + a];
        float ws = gws[n * 3 + a];
        float wl = gwl[n * 3 + a];
        float4 vs = *reinterpret_cast<const float4*>(base + a * 128 + is * 16);
        float4 vl = *reinterpret_cast<const float4*>(base + a * 128 + il * 16);
        f.x *= vs.x * ws + vl.x * wl;
        f.y *= vs.y * ws + vl.y * wl;
        f.z *= vs.z * ws + vl.z * wl;
        f.w *= vs.w * ws + vl.w * wl;
    }

    float4 dn = *reinterpret_cast<const float4*>(densities + (size_t)p * 16 + q * 4);
    float sig = f.x * dn.x + f.y * dn.y + f.z * dn.z + f.w * dn.w;

    const float* cb = colors + (size_t)p * 48 + q * 12;
    float4 c0 = *reinterpret_cast<const float4*>(cb);
    float4 c1 = *reinterpret_cast<const float4*>(cb + 4);
    float4 c2 = *reinterpret_cast<const float4*>(cb + 8);
    // layout (c,k): c0={f0k0,f0k1,f0k2,f1k0} c1={f1k1,f1k2,f2k0,f2k1} c2={f2k2,f3k0,f3k1,f3k2}
    float cr = f.x * c0.x + f.y * c0.w + f.z * c1.z + f.w * c2.y;
    float cg = f.x * c0.y + f.y * c1.x + f.z * c1.w + f.w * c2.z;
    float cbv = f.x * c0.z + f.y * c1.y + f.z * c2.x + f.w * c2.w;

    // quad reduction (lanes q^1, q^2)
    #pragma unroll
    for (int m = 1; m < 4; m <<= 1) {
        sig += __shfl_xor_sync(0xffffffffu, sig, m);
        cr  += __shfl_xor_sync(0xffffffffu, cr,  m);
        cg  += __shfl_xor_sync(0xffffffffu, cg,  m);
        cbv += __shfl_xor_sync(0xffffffffu, cbv, m);
    }

    if (q == 0) {
        // DENSITY_SHIFT = 0, DENSITY_SCALE = 1
        float density = (sig > 15.f) ? sig : log1pf(__expf(sig));
        float lt = -density * STEP_SIZE;
        float alpha = 1.f - __expf(lt);
        float rr = 1.f / (1.f + __expf(-cr));
        float rg = 1.f / (1.f + __expf(-cg));
        float rb = 1.f / (1.f + __expf(-cbv));
        g_samp[n] = make_float4(alpha, rr, rg, rb);
        g_logt[n] = lt;
    }
}

// ---------------------------------------------------------------------------
// Kernel 3: per-ray segmented scan (ray_id is sorted, segments contiguous).
// One thread per ray; binary-search segment bounds.
// ---------------------------------------------------------------------------
__global__ __launch_bounds__(256) void ray_k(
    const int*   __restrict__ ray_id,
    const int*   __restrict__ step_id,
    const float* __restrict__ t_min,
    const float* __restrict__ bg,
    float*       __restrict__ out)
{
    int r = blockIdx.x * blockDim.x + threadIdx.x;
    if (r >= N_RAYS) return;

    // lower_bound(r)
    int lo = 0, hi = N_SAMPLES;
    while (lo < hi) {
        int mid = (lo + hi) >> 1;
        if (ray_id[mid] < r) lo = mid + 1; else hi = mid;
    }
    int s = lo;
    // lower_bound(r+1)
    hi = N_SAMPLES;
    while (lo < hi) {
        int mid = (lo + hi) >> 1;
        if (ray_id[mid] <= r) lo = mid + 1; else hi = mid;
    }
    int e = lo;

    float T = 0.f;
    float ra = 0.f, ga = 0.f, ba = 0.f, da = 0.f;
    float tm = t_min[r];
    for (int j = s; j < e; j++) {
        float4 sp = g_samp[j];
        float w = sp.x * __expf(T);
        ra += w * sp.y;
        ga += w * sp.z;
        ba += w * sp.w;
        da += w * (tm + (float)step_id[j] * STEP_SIZE);
        T += g_logt[j];
    }
    float bgw = __expf(T);
    out[0 * N_RAYS + r] = ra + bgw * bg[0];
    out[1 * N_RAYS + r] = ga + bgw * bg[1];
    out[2 * N_RAYS + r] = ba + bgw * bg[2];
    out[3 * N_RAYS + r] = da;            // depth map
    out[4 * N_RAYS + r] = 1.f - bgw;     // alpha map
}

extern "C" void kernel_launch(void* const* d_in, const int* in_sizes, int n_in,
                              void* d_out, int out_size) {
    const float* trivecs   = (const float*)d_in[0];
    const float* densities = (const float*)d_in[1];
    const float* colors    = (const float*)d_in[2];
    const float* gws       = (const float*)d_in[3];
    const float* gwl       = (const float*)d_in[4];
    const float* t_min     = (const float*)d_in[5];
    const float* bg        = (const float*)d_in[6];
    const int*   gis       = (const int*)d_in[7];
    const int*   gil       = (const int*)d_in[8];
    const int*   tfid      = (const int*)d_in[9];
    const int*   ray_id    = (const int*)d_in[10];
    const int*   step_id   = (const int*)d_in[11];
    float* out = (float*)d_out;

    transpose_k<<<P_CNT, 128>>>(trivecs);
    sample_k<<<(4 * N_SAMPLES + 255) / 256, 256>>>(densities, colors, gws, gwl, gis, gil, tfid);
    ray_k<<<(N_RAYS + 255) / 256, 256>>>(ray_id, step_id, t_min, bg, out);
}

// round 4
// speedup vs baseline: 1.0209x; 1.0209x over previous
#include <cuda_runtime.h>
#include <cuda_bf16.h>

#define Hh 250
#define Ww 400
#define N_RAYS (Hh*Ww)            // 100000
#define N_SAMPLES 1000000
#define P_CNT 50000
#define STEP_SIZE 0.005f
#define PBLK 384                  // C*3*DIM floats per p
#define PPAD 416                  // 16 rows of 24 floats padded to 26

// Scratch (static device allocations are permitted)
__device__ float  g_trivecsT[(size_t)P_CNT * PBLK];   // (P, 3, DIM, C), ~76.8MB
__device__ float4 g_samp[N_SAMPLES];                  // {alpha, r, g, b}
__device__ float  g_z[N_SAMPLES];                     // z value per sample
__device__ int    g_start[N_RAYS];                    // segment start per ray
__device__ int    g_end[N_RAYS];                      // segment end per ray

// ---------------------------------------------------------------------------
// Kernel 0: init segment bounds (empty rays -> s == e == 0).
// ---------------------------------------------------------------------------
__global__ __launch_bounds__(256) void init_k() {
    int r = blockIdx.x * blockDim.x + threadIdx.x;
    if (r < N_RAYS) { g_start[r] = 0; g_end[r] = 0; }
}

// ---------------------------------------------------------------------------
// Kernel 1: transpose trivecs (P,C,3,DIM) -> (P,3,DIM,C).
// 4 p-blocks per 384-thread block; float4 coalesced loads/stores; smem row
// stride 26 => conflict-free permuted reads. (24 % 4 == 0: no row straddle.)
// ---------------------------------------------------------------------------
__global__ __launch_bounds__(384) void transpose_k(const float4* __restrict__ in) {
    __shared__ float sm[4 * PPAD];
    int t = threadIdx.x;
    size_t base4 = (size_t)blockIdx.x * 384;   // float4 index of this 4-p group

    float4 v = in[base4 + t];
    int m  = t * 4;                 // float offset within group
    int pl = t / 96;                // local p (96 float4 per p)
    int mo = m - pl * PBLK;         // 0..383 (mult of 4): row = mo/24 (c), col = mo%24 (a*8+d)
    int pi = mo + 2 * (mo / 24);    // padded index
    float* s = sm + pl * PPAD;
    s[pi + 0] = v.x; s[pi + 1] = v.y; s[pi + 2] = v.z; s[pi + 3] = v.w;
    __syncthreads();

    // output element mo in layout a*128 + d*16 + c; this thread covers c..c+3
    int c = mo & 15, d = (mo >> 4) & 7, a = mo >> 7;
    const float* s2 = sm + pl * PPAD;
    int i0 = c * 26 + a * 8 + d;    // c in {0,4,8,12}: i0+78 <= 413 < 416
    float4 w = make_float4(s2[i0], s2[i0 + 26], s2[i0 + 52], s2[i0 + 78]);
    reinterpret_cast<float4*>(g_trivecsT)[base4 + pl * 96 + a * 32 + d * 4 + (c >> 2)] = w;
}

// ---------------------------------------------------------------------------
// Kernel 2: per-sample feature/sigma/color (+ z, + segment boundaries).
// 4 threads per sample, 4 channels each via float4; quad shuffle-reduce.
// ---------------------------------------------------------------------------
__global__ __launch_bounds__(256) void sample_k(
    const float* __restrict__ densities,   // (P, 16)
    const float* __restrict__ colors,      // (P, 16, 3)
    const float* __restrict__ gws,         // (N, 3)
    const float* __restrict__ gwl,         // (N, 3)
    const int*   __restrict__ gis,         // (N, 3)
    const int*   __restrict__ gil,         // (N, 3)
    const int*   __restrict__ tfid,        // (N,)
    const int*   __restrict__ ray_id,      // (N,) sorted
    const int*   __restrict__ step_id,     // (N,)
    const float* __restrict__ t_min)       // (N_RAYS,)
{
    int t = blockIdx.x * blockDim.x + threadIdx.x;
    int n = t >> 2;
    if (n >= N_SAMPLES) return;
    int q = t & 3;

    int p = tfid[n];
    const float* base = g_trivecsT + (size_t)p * PBLK + q * 4;

    float4 f = make_float4(1.f, 1.f, 1.f, 1.f);
    #pragma unroll
    for (int a = 0; a < 3; a++) {
        int   is = gis[n * 3 + a];
        int   il = gil[n * 3 + a];
        float ws = gws[n * 3 + a];
        float wl = gwl[n * 3 + a];
        float4 vs = *reinterpret_cast<const float4*>(base + a * 128 + is * 16);
        float4 vl = *reinterpret_cast<const float4*>(base + a * 128 + il * 16);
        f.x *= vs.x * ws + vl.x * wl;
        f.y *= vs.y * ws + vl.y * wl;
        f.z *= vs.z * ws + vl.z * wl;
        f.w *= vs.w * ws + vl.w * wl;
    }

    float4 dn = *reinterpret_cast<const float4*>(densities + (size_t)p * 16 + q * 4);
    float sig = f.x * dn.x + f.y * dn.y + f.z * dn.z + f.w * dn.w;

    const float* cb = colors + (size_t)p * 48 + q * 12;
    float4 c0 = *reinterpret_cast<const float4*>(cb);
    float4 c1 = *reinterpret_cast<const float4*>(cb + 4);
    float4 c2 = *reinterpret_cast<const float4*>(cb + 8);
    float cr  = f.x * c0.x + f.y * c0.w + f.z * c1.z + f.w * c2.y;
    float cg  = f.x * c0.y + f.y * c1.x + f.z * c1.w + f.w * c2.z;
    float cbv = f.x * c0.z + f.y * c1.y + f.z * c2.x + f.w * c2.w;

    #pragma unroll
    for (int m = 1; m < 4; m <<= 1) {
        sig += __shfl_xor_sync(0xffffffffu, sig, m);
        cr  += __shfl_xor_sync(0xffffffffu, cr,  m);
        cg  += __shfl_xor_sync(0xffffffffu, cg,  m);
        cbv += __shfl_xor_sync(0xffffffffu, cbv, m);
    }

    if (q == 0) {
        // DENSITY_SHIFT = 0, DENSITY_SCALE = 1
        float density = (sig > 15.f) ? sig : log1pf(__expf(sig));
        float alpha = 1.f - __expf(-density * STEP_SIZE);
        float rr = 1.f / (1.f + __expf(-cr));
        float rg = 1.f / (1.f + __expf(-cg));
        float rb = 1.f / (1.f + __expf(-cbv));
        g_samp[n] = make_float4(alpha, rr, rg, rb);
        int r = ray_id[n];
        g_z[n] = t_min[r] + (float)step_id[n] * STEP_SIZE;
    } else if (q == 1) {
        // boundary writes only — no loops (empty rays stay s == e == 0)
        int r = ray_id[n];
        if (n == 0 || ray_id[n - 1] != r)             g_start[r] = n;
        if (n == N_SAMPLES - 1 || ray_id[n + 1] != r) g_end[r]   = n + 1;
    }
}

// ---------------------------------------------------------------------------
// Kernel 3: per-ray composite. Multiplicative transmittance: no exp in loop.
// ---------------------------------------------------------------------------
__global__ __launch_bounds__(256) void ray_k(
    const float* __restrict__ bg,
    float*       __restrict__ out)
{
    int r = blockIdx.x * blockDim.x + threadIdx.x;
    if (r >= N_RAYS) return;

    int s = g_start[r];
    int e = g_end[r];

    float T = 1.f;                     // transmittance = prod(1 - alpha)
    float ra = 0.f, ga = 0.f, ba = 0.f, da = 0.f;
    for (int j = s; j < e; j++) {
        float4 sp = g_samp[j];
        float w = sp.x * T;
        ra += w * sp.y;
        ga += w * sp.z;
        ba += w * sp.w;
        da += w * g_z[j];
        T *= (1.f - sp.x);
    }
    out[0 * N_RAYS + r] = ra + T * __ldg(bg + 0);
    out[1 * N_RAYS + r] = ga + T * __ldg(bg + 1);
    out[2 * N_RAYS + r] = ba + T * __ldg(bg + 2);
    out[3 * N_RAYS + r] = da;          // depth map
    out[4 * N_RAYS + r] = 1.f - T;     // alpha map
}

extern "C" void kernel_launch(void* const* d_in, const int* in_sizes, int n_in,
                              void* d_out, int out_size) {
    const float* trivecs   = (const float*)d_in[0];
    const float* densities = (const float*)d_in[1];
    const float* colors    = (const float*)d_in[2];
    const float* gws       = (const float*)d_in[3];
    const float* gwl       = (const float*)d_in[4];
    const float* t_min     = (const float*)d_in[5];
    const float* bg        = (const float*)d_in[6];
    const int*   gis       = (const int*)d_in[7];
    const int*   gil       = (const int*)d_in[8];
    const int*   tfid      = (const int*)d_in[9];
    const int*   ray_id    = (const int*)d_in[10];
    const int*   step_id   = (const int*)d_in[11];
    float* out = (float*)d_out;

    init_k<<<(N_RAYS + 255) / 256, 256>>>();
    transpose_k<<<P_CNT / 4, 384>>>((const float4*)trivecs);
    sample_k<<<(4 * N_SAMPLES + 255) / 256, 256>>>(densities, colors, gws, gwl,
                                                   gis, gil, tfid, ray_id, step_id, t_min);
    ray_k<<<(N_RAYS + 255) / 256, 256>>>(bg, out);
}

// round 5
// speedup vs baseline: 1.3365x; 1.3092x over previous
#include <cuda_runtime.h>
#include <cuda_fp16.h>

#define Hh 250
#define Ww 400
#define N_RAYS (Hh*Ww)            // 100000
#define N_SAMPLES 1000000
#define P_CNT 50000
#define STEP_SIZE 0.005f
#define PBLK 384                  // C*3*DIM elems per p
#define PPAD 416                  // 16 rows of 24 floats padded to 26

// Scratch (static device allocations are permitted)
__device__ __half  g_trivecsH[(size_t)P_CNT * PBLK];  // (P,3,DIM,C) half, ~38.4MB
__device__ __half  g_colorsH[(size_t)P_CNT * 48];     // (P,16,3) half, ~4.8MB
__device__ float4  g_samp[N_SAMPLES];                 // {alpha, r, g, b}
__device__ int     g_start[N_RAYS];
__device__ int     g_end[N_RAYS];

// ---------------------------------------------------------------------------
// Kernel 1: transpose trivecs (P,C,3,DIM) fp32 -> (P,3,DIM,C) fp16.
// Also converts colors to fp16 and zeroes the segment tables (folded in).
// 4 p-blocks per 384-thread block; float4 loads, uint2(4x half) stores;
// smem row stride 26 => conflict-free permuted reads.
// ---------------------------------------------------------------------------
__global__ __launch_bounds__(384) void transpose_k(const float4* __restrict__ in,
                                                   const float4* __restrict__ colors4) {
    __shared__ float sm[4 * PPAD];
    int t = threadIdx.x;
    int gid = blockIdx.x * 384 + t;
    size_t base4 = (size_t)blockIdx.x * 384;   // float4 index of this 4-p group

    float4 v = in[base4 + t];

    // folded init of segment tables (12500*384 = 4.8M threads covers 100k)
    if (gid < N_RAYS) { g_start[gid] = 0; g_end[gid] = 0; }
    // folded colors fp32 -> fp16 (P*48 floats = 600000 float4)
    if (gid < P_CNT * 12) {
        float4 c = colors4[gid];
        union { __half2 h[2]; uint2 u; } cv;
        cv.h[0] = __floats2half2_rn(c.x, c.y);
        cv.h[1] = __floats2half2_rn(c.z, c.w);
        reinterpret_cast<uint2*>(g_colorsH)[gid] = cv.u;
    }

    int m  = t * 4;                 // float offset within group
    int pl = t / 96;                // local p (96 float4 per p)
    int mo = m - pl * PBLK;         // 0..383 (mult of 4): row = mo/24 (c), col = mo%24 (a*8+d)
    int pi = mo + 2 * (mo / 24);    // padded index
    float* s = sm + pl * PPAD;
    s[pi + 0] = v.x; s[pi + 1] = v.y; s[pi + 2] = v.z; s[pi + 3] = v.w;
    __syncthreads();

    // output element mo in layout a*128 + d*16 + c; this thread covers c..c+3
    int c = mo & 15, d = (mo >> 4) & 7, a = mo >> 7;
    const float* s2 = sm + pl * PPAD;
    int i0 = c * 26 + a * 8 + d;
    union { __half2 h[2]; uint2 u; } ov;
    ov.h[0] = __floats2half2_rn(s2[i0],      s2[i0 + 26]);
    ov.h[1] = __floats2half2_rn(s2[i0 + 52], s2[i0 + 78]);
    reinterpret_cast<uint2*>(g_trivecsH)[base4 + pl * 96 + a * 32 + d * 4 + (c >> 2)] = ov.u;
}

// ---------------------------------------------------------------------------
// Kernel 2: per-sample feature/sigma/color (+ segment boundaries).
// 4 threads per sample, 4 channels each via 8B half loads; quad shuffle-reduce.
// ---------------------------------------------------------------------------
__global__ __launch_bounds__(256) void sample_k(
    const float* __restrict__ densities,   // (P, 16) fp32
    const float* __restrict__ gws,         // (N, 3)
    const float* __restrict__ gwl,         // (N, 3)
    const int*   __restrict__ gis,         // (N, 3)
    const int*   __restrict__ gil,         // (N, 3)
    const int*   __restrict__ tfid,        // (N,)
    const int*   __restrict__ ray_id)      // (N,) sorted
{
    int t = blockIdx.x * blockDim.x + threadIdx.x;
    int n = t >> 2;
    if (n >= N_SAMPLES) return;
    int q = t & 3;

    int p = tfid[n];
    const __half* base = g_trivecsH + (size_t)p * PBLK + q * 4;

    float4 f = make_float4(1.f, 1.f, 1.f, 1.f);
    #pragma unroll
    for (int a = 0; a < 3; a++) {
        int   is = gis[n * 3 + a];
        int   il = gil[n * 3 + a];
        float ws = gws[n * 3 + a];
        float wl = gwl[n * 3 + a];
        uint2 rs = *reinterpret_cast<const uint2*>(base + a * 128 + is * 16);
        uint2 rl = *reinterpret_cast<const uint2*>(base + a * 128 + il * 16);
        float2 vs0 = __half22float2(*reinterpret_cast<const __half2*>(&rs.x));
        float2 vs1 = __half22float2(*reinterpret_cast<const __half2*>(&rs.y));
        float2 vl0 = __half22float2(*reinterpret_cast<const __half2*>(&rl.x));
        float2 vl1 = __half22float2(*reinterpret_cast<const __half2*>(&rl.y));
        f.x *= vs0.x * ws + vl0.x * wl;
        f.y *= vs0.y * ws + vl0.y * wl;
        f.z *= vs1.x * ws + vl1.x * wl;
        f.w *= vs1.y * ws + vl1.y * wl;
    }

    float4 dn = *reinterpret_cast<const float4*>(densities + (size_t)p * 16 + q * 4);
    float sig = f.x * dn.x + f.y * dn.y + f.z * dn.z + f.w * dn.w;

    // colors: lane q covers halves [q*12, q*12+12) of the p's 48-half block
    const __half* cbh = g_colorsH + (size_t)p * 48 + q * 12;
    uint2 u0 = *reinterpret_cast<const uint2*>(cbh);
    uint2 u1 = *reinterpret_cast<const uint2*>(cbh + 4);
    uint2 u2 = *reinterpret_cast<const uint2*>(cbh + 8);
    float2 h01 = __half22float2(*reinterpret_cast<const __half2*>(&u0.x));
    float2 h23 = __half22float2(*reinterpret_cast<const __half2*>(&u0.y));
    float2 h45 = __half22float2(*reinterpret_cast<const __half2*>(&u1.x));
    float2 h67 = __half22float2(*reinterpret_cast<const __half2*>(&u1.y));
    float2 h89 = __half22float2(*reinterpret_cast<const __half2*>(&u2.x));
    float2 hAB = __half22float2(*reinterpret_cast<const __half2*>(&u2.y));
    // element (c_local, k): index c_local*3 + k
    float cr  = f.x * h01.x + f.y * h23.y + f.z * h67.x + f.w * h89.y;
    float cg  = f.x * h01.y + f.y * h45.x + f.z * h67.y + f.w * hAB.x;
    float cbv = f.x * h23.x + f.y * h45.y + f.z * h89.x + f.w * hAB.y;

    #pragma unroll
    for (int m = 1; m < 4; m <<= 1) {
        sig += __shfl_xor_sync(0xffffffffu, sig, m);
        cr  += __shfl_xor_sync(0xffffffffu, cr,  m);
        cg  += __shfl_xor_sync(0xffffffffu, cg,  m);
        cbv += __shfl_xor_sync(0xffffffffu, cbv, m);
    }

    if (q == 0) {
        // DENSITY_SHIFT = 0, DENSITY_SCALE = 1
        float density = (sig > 15.f) ? sig : log1pf(__expf(sig));
        float alpha = 1.f - __expf(-density * STEP_SIZE);
        float rr = 1.f / (1.f + __expf(-cr));
        float rg = 1.f / (1.f + __expf(-cg));
        float rb = 1.f / (1.f + __expf(-cbv));
        g_samp[n] = make_float4(alpha, rr, rg, rb);
    } else if (q == 1) {
        // boundary writes only — no loops (empty rays stay s == e == 0)
        int r = ray_id[n];
        if (n == 0 || ray_id[n - 1] != r)             g_start[r] = n;
        if (n == N_SAMPLES - 1 || ray_id[n + 1] != r) g_end[r]   = n + 1;
    }
}

// ---------------------------------------------------------------------------
// Kernel 3: per-ray composite. Multiplicative transmittance, 1-deep prefetch.
// ---------------------------------------------------------------------------
__global__ __launch_bounds__(256) void ray_k(
    const int*   __restrict__ step_id,
    const float* __restrict__ t_min,
    const float* __restrict__ bg,
    float*       __restrict__ out)
{
    int r = blockIdx.x * blockDim.x + threadIdx.x;
    if (r >= N_RAYS) return;

    int s = g_start[r];
    int e = g_end[r];
    float tm = t_min[r];

    float T = 1.f;
    float ra = 0.f, ga = 0.f, ba = 0.f, da = 0.f;
    float4 sp; int st = 0;
    if (s < e) { sp = g_samp[s]; st = step_id[s]; }
    for (int j = s; j < e; j++) {
        float4 cur = sp;
        int    cst = st;
        if (j + 1 < e) { sp = g_samp[j + 1]; st = step_id[j + 1]; }
        float w = cur.x * T;
        ra += w * cur.y;
        ga += w * cur.z;
        ba += w * cur.w;
        da += w * (tm + (float)cst * STEP_SIZE);
        T *= (1.f - cur.x);
    }
    out[0 * N_RAYS + r] = ra + T * __ldg(bg + 0);
    out[1 * N_RAYS + r] = ga + T * __ldg(bg + 1);
    out[2 * N_RAYS + r] = ba + T * __ldg(bg + 2);
    out[3 * N_RAYS + r] = da;          // depth map
    out[4 * N_RAYS + r] = 1.f - T;     // alpha map
}

extern "C" void kernel_launch(void* const* d_in, const int* in_sizes, int n_in,
                              void* d_out, int out_size) {
    const float* trivecs   = (const float*)d_in[0];
    const float* densities = (const float*)d_in[1];
    const float* colors    = (const float*)d_in[2];
    const float* gws       = (const float*)d_in[3];
    const float* gwl       = (const float*)d_in[4];
    const float* t_min     = (const float*)d_in[5];
    const float* bg        = (const float*)d_in[6];
    const int*   gis       = (const int*)d_in[7];
    const int*   gil       = (const int*)d_in[8];
    const int*   tfid      = (const int*)d_in[9];
    const int*   ray_id    = (const int*)d_in[10];
    const int*   step_id   = (const int*)d_in[11];
    float* out = (float*)d_out;

    transpose_k<<<P_CNT / 4, 384>>>((const float4*)trivecs, (const float4*)colors);
    sample_k<<<(4 * N_SAMPLES + 255) / 256, 256>>>(densities, gws, gwl,
                                                   gis, gil, tfid, ray_id);
    ray_k<<<(N_RAYS + 255) / 256, 256>>>(step_id, t_min, bg, out);
}

// round 7
// speedup vs baseline: 1.4731x; 1.1022x over previous
#include <cuda_runtime.h>
#include <cuda_fp16.h>

#define Hh 250
#define Ww 400
#define N_RAYS (Hh*Ww)            // 100000
#define N_SAMPLES 1000000
#define P_CNT 50000
#define STEP_SIZE 0.005f
#define PBLK 384                  // C*3*DIM elems per p
#define PPAD 416                  // 16 rows of 24 floats padded to 26

// Scratch (static device allocations are permitted)
__device__ __half  g_trivecsH[(size_t)P_CNT * PBLK];  // (P,3,DIM,C) half, ~38.4MB
__device__ __half  g_dc[(size_t)P_CNT * 64];          // per p: 16 dens + 48 colors halves (128B)
__device__ float4  g_samp[N_SAMPLES];                 // {alpha, r, g, b}
__device__ int     g_start[N_RAYS];
__device__ int     g_end[N_RAYS];

// ---------------------------------------------------------------------------
// Kernel 1: transpose trivecs (P,C,3,DIM) fp32 -> (P,3,DIM,C) fp16.
// Two 4-p groups per 384-thread block (index math amortized, 2x MLP).
// Folds in: densities+colors fp32->fp16 pack, segment-table zeroing.
// ---------------------------------------------------------------------------
__global__ __launch_bounds__(384) void transpose_k(const float4* __restrict__ in,
                                                   const float4* __restrict__ densities4,
                                                   const float4* __restrict__ colors4) {
    __shared__ float sm[8 * PPAD];
    int t = threadIdx.x;
    int gid = blockIdx.x * 384 + t;            // up to 2.4M
    size_t base4 = (size_t)blockIdx.x * 768;   // float4 index of first 4-p group

    float4 v0 = __ldcs(in + base4 + t);
    float4 v1 = __ldcs(in + base4 + 384 + t);

    // folded init of segment tables
    if (gid < N_RAYS) { g_start[gid] = 0; g_end[gid] = 0; }
    // folded densities+colors fp32 -> fp16 pack: out block p = 64 halves
    // [0:16) = densities, [16:64) = colors (c*3+k). Thread handles 4 floats.
    if (gid < P_CNT * 16) {
        int p = gid >> 4;
        int o = (gid & 15) * 4;                // 0,4,...,60
        float4 src = (o < 16)
            ? __ldcs(densities4 + ((size_t)p * 16 + o) / 4)
            : __ldcs(colors4    + ((size_t)p * 48 + (o - 16)) / 4);
        union { __half2 h[2]; uint2 u; } cv;
        cv.h[0] = __floats2half2_rn(src.x, src.y);
        cv.h[1] = __floats2half2_rn(src.z, src.w);
        reinterpret_cast<uint2*>(g_dc)[(size_t)p * 16 + (o >> 2)] = cv.u;
    }

    int m  = t * 4;                 // float offset within a 4-p group
    int pl = t / 96;                // local p (96 float4 per p)
    int mo = m - pl * PBLK;         // 0..383: row = mo/24 (c), col = mo%24 (a*8+d)
    int pi = mo + 2 * (mo / 24);    // padded index
    float* s0 = sm + pl * PPAD;
    float* s1 = sm + (4 + pl) * PPAD;
    s0[pi + 0] = v0.x; s0[pi + 1] = v0.y; s0[pi + 2] = v0.z; s0[pi + 3] = v0.w;
    s1[pi + 0] = v1.x; s1[pi + 1] = v1.y; s1[pi + 2] = v1.z; s1[pi + 3] = v1.w;
    __syncthreads();

    int c = mo & 15, d = (mo >> 4) & 7, a = mo >> 7;
    int i0 = c * 26 + a * 8 + d;
    const float* r0 = sm + pl * PPAD;
    const float* r1 = sm + (4 + pl) * PPAD;
    union { __half2 h[2]; uint2 u; } o0, o1;
    o0.h[0] = __floats2half2_rn(r0[i0],      r0[i0 + 26]);
    o0.h[1] = __floats2half2_rn(r0[i0 + 52], r0[i0 + 78]);
    o1.h[0] = __floats2half2_rn(r1[i0],      r1[i0 + 26]);
    o1.h[1] = __floats2half2_rn(r1[i0 + 52], r1[i0 + 78]);
    int oidx = pl * 96 + a * 32 + d * 4 + (c >> 2);
    uint2* outp = reinterpret_cast<uint2*>(g_trivecsH);
    outp[base4 + oidx]       = o0.u;
    outp[base4 + 384 + oidx] = o1.u;
}

// ---------------------------------------------------------------------------
// Kernel 2: per-sample feature/sigma/color (+ segment boundaries).
// 4 threads per sample, 4 channels each; quad shuffle-reduce.
// ---------------------------------------------------------------------------
__global__ __launch_bounds__(256) void sample_k(
    const float* __restrict__ gws,         // (N, 3)
    const float* __restrict__ gwl,         // (N, 3)
    const int*   __restrict__ gis,         // (N, 3)
    const int*   __restrict__ gil,         // (N, 3)
    const int*   __restrict__ tfid,        // (N,)
    const int*   __restrict__ ray_id)      // (N,) sorted
{
    int t = blockIdx.x * blockDim.x + threadIdx.x;
    int n = t >> 2;
    if (n >= N_SAMPLES) return;
    int q = t & 3;

    int p = __ldcs(tfid + n);
    const __half* base = g_trivecsH + (size_t)p * PBLK + q * 4;

    float4 f = make_float4(1.f, 1.f, 1.f, 1.f);
    #pragma unroll
    for (int a = 0; a < 3; a++) {
        int   is = __ldcs(gis + n * 3 + a);
        int   il = __ldcs(gil + n * 3 + a);
        float ws = __ldcs(gws + n * 3 + a);
        float wl = __ldcs(gwl + n * 3 + a);
        uint2 rs = *reinterpret_cast<const uint2*>(base + a * 128 + is * 16);
        uint2 rl = *reinterpret_cast<const uint2*>(base + a * 128 + il * 16);
        float2 vs0 = __half22float2(*reinterpret_cast<const __half2*>(&rs.x));
        float2 vs1 = __half22float2(*reinterpret_cast<const __half2*>(&rs.y));
        float2 vl0 = __half22float2(*reinterpret_cast<const __half2*>(&rl.x));
        float2 vl1 = __half22float2(*reinterpret_cast<const __half2*>(&rl.y));
        f.x *= vs0.x * ws + vl0.x * wl;
        f.y *= vs0.y * ws + vl0.y * wl;
        f.z *= vs1.x * ws + vl1.x * wl;
        f.w *= vs1.y * ws + vl1.y * wl;
    }

    // densities: halves [q*4, q*4+4) of p's 64-half block
    const __half* dch = g_dc + (size_t)p * 64;
    uint2 du = *reinterpret_cast<const uint2*>(dch + q * 4);
    float2 d01 = __half22float2(*reinterpret_cast<const __half2*>(&du.x));
    float2 d23 = __half22float2(*reinterpret_cast<const __half2*>(&du.y));
    float sig = f.x * d01.x + f.y * d01.y + f.z * d23.x + f.w * d23.y;

    // colors: halves [16 + q*12, 16 + q*12 + 12), element (c_local,k) at c_local*3+k
    const __half* cbh = dch + 16 + q * 12;
    uint2 u0 = *reinterpret_cast<const uint2*>(cbh);
    uint2 u1 = *reinterpret_cast<const uint2*>(cbh + 4);
    uint2 u2 = *reinterpret_cast<const uint2*>(cbh + 8);
    float2 h01 = __half22float2(*reinterpret_cast<const __half2*>(&u0.x));
    float2 h23 = __half22float2(*reinterpret_cast<const __half2*>(&u0.y));
    float2 h45 = __half22float2(*reinterpret_cast<const __half2*>(&u1.x));
    float2 h67 = __half22float2(*reinterpret_cast<const __half2*>(&u1.y));
    float2 h89 = __half22float2(*reinterpret_cast<const __half2*>(&u2.x));
    float2 hAB = __half22float2(*reinterpret_cast<const __half2*>(&u2.y));
    float cr  = f.x * h01.x + f.y * h23.y + f.z * h67.x + f.w * h89.y;
    float cg  = f.x * h01.y + f.y * h45.x + f.z * h67.y + f.w * hAB.x;
    float cbv = f.x * h23.x + f.y * h45.y + f.z * h89.x + f.w * hAB.y;

    #pragma unroll
    for (int m = 1; m < 4; m <<= 1) {
        sig += __shfl_xor_sync(0xffffffffu, sig, m);
        cr  += __shfl_xor_sync(0xffffffffu, cr,  m);
        cg  += __shfl_xor_sync(0xffffffffu, cg,  m);
        cbv += __shfl_xor_sync(0xffffffffu, cbv, m);
    }

    if (q == 0) {
        // DENSITY_SHIFT = 0, DENSITY_SCALE = 1
        float density = (sig > 15.f) ? sig : log1pf(__expf(sig));
        float alpha = 1.f - __expf(-density * STEP_SIZE);
        float rr = 1.f / (1.f + __expf(-cr));
        float rg = 1.f / (1.f + __expf(-cg));
        float rb = 1.f / (1.f + __expf(-cbv));
        g_samp[n] = make_float4(alpha, rr, rg, rb);
    } else if (q == 1) {
        int r = __ldcs(ray_id + n);
        int rp = (n > 0) ? __ldcs(ray_id + n - 1) : -1;
        int rn = (n < N_SAMPLES - 1) ? __ldcs(ray_id + n + 1) : -1;
        if (rp != r) g_start[r] = n;
        if (rn != r) g_end[r]   = n + 1;
    }
}

// ---------------------------------------------------------------------------
// Kernel 3: per-ray composite. Multiplicative transmittance, 1-deep prefetch.
// ---------------------------------------------------------------------------
__global__ __launch_bounds__(256) void ray_k(
    const int*   __restrict__ step_id,
    const float* __restrict__ t_min,
    const float* __restrict__ bg,
    float*       __restrict__ out)
{
    int r = blockIdx.x * blockDim.x + threadIdx.x;
    if (r >= N_RAYS) return;

    int s = g_start[r];
    int e = g_end[r];
    float tm = t_min[r];

    float T = 1.f;
    float ra = 0.f, ga = 0.f, ba = 0.f, da = 0.f;
    float4 sp; int st = 0;
    if (s < e) { sp = __ldcs(g_samp + s); st = __ldcs(step_id + s); }
    for (int j = s; j < e; j++) {
        float4 cur = sp;
        int    cst = st;
        if (j + 1 < e) { sp = __ldcs(g_samp + j + 1); st = __ldcs(step_id + j + 1); }
        float w = cur.x * T;
        ra += w * cur.y;
        ga += w * cur.z;
        ba += w * cur.w;
        da += w * (tm + (float)cst * STEP_SIZE);
        T *= (1.f - cur.x);
    }
    out[0 * N_RAYS + r] = ra + T * __ldg(bg + 0);
    out[1 * N_RAYS + r] = ga + T * __ldg(bg + 1);
    out[2 * N_RAYS + r] = ba + T * __ldg(bg + 2);
    out[3 * N_RAYS + r] = da;          // depth map
    out[4 * N_RAYS + r] = 1.f - T;     // alpha map
}

extern "C" void kernel_launch(void* const* d_in, const int* in_sizes, int n_in,
                              void* d_out, int out_size) {
    const float* trivecs   = (const float*)d_in[0];
    const float* densities = (const float*)d_in[1];
    const float* colors    = (const float*)d_in[2];
    const float* gws       = (const float*)d_in[3];
    const float* gwl       = (const float*)d_in[4];
    const float* t_min     = (const float*)d_in[5];
    const float* bg        = (const float*)d_in[6];
    const int*   gis       = (const int*)d_in[7];
    const int*   gil       = (const int*)d_in[8];
    const int*   tfid      = (const int*)d_in[9];
    const int*   ray_id    = (const int*)d_in[10];
    const int*   step_id   = (const int*)d_in[11];
    float* out = (float*)d_out;

    transpose_k<<<P_CNT / 8, 384>>>((const float4*)trivecs,
                                    (const float4*)densities,
                                    (const float4*)colors);
    sample_k<<<(4 * N_SAMPLES + 255) / 256, 256>>>(gws, gwl, gis, gil, tfid, ray_id);
    ray_k<<<(N_RAYS + 255) / 256, 256>>>(step_id, t_min, bg, out);
}

// round 11
// speedup vs baseline: 1.4871x; 1.0095x over previous
#include <cuda_runtime.h>
#include <cuda_fp16.h>

#define Hh 250
#define Ww 400
#define N_RAYS (Hh*Ww)            // 100000
#define N_SAMPLES 1000000
#define P_CNT 50000
#define STEP_SIZE 0.005f
#define PBLK 384                  // C*3*DIM elems per p
#define PPAD 416                  // 16 rows of 24 floats padded to 26

// Scratch (static device allocations are permitted)
__device__ __half  g_trivecsH[(size_t)P_CNT * PBLK];  // (P,3,DIM,C) half, ~38.4MB
__device__ __half  g_dc[(size_t)P_CNT * 64];          // per p: 16 dens + 48 colors halves (128B)
__device__ float4  g_samp[N_SAMPLES];                 // {alpha, r, g, b}
__device__ int     g_start[N_RAYS];
__device__ int     g_end[N_RAYS];

// ---------------------------------------------------------------------------
// Kernel 1: transpose trivecs (P,C,3,DIM) fp32 -> (P,3,DIM,C) fp16.
// Four 4-p groups per 384-thread block (4x MLP, index math amortized).
// Folds in: densities+colors fp32->fp16 pack, segment-table zeroing.
// ---------------------------------------------------------------------------
__global__ __launch_bounds__(384) void transpose_k(const float4* __restrict__ in,
                                                   const float4* __restrict__ densities4,
                                                   const float4* __restrict__ colors4) {
    __shared__ float sm[16 * PPAD];
    int t = threadIdx.x;
    int gid = blockIdx.x * 384 + t;            // up to 1.2M
    size_t base4 = (size_t)blockIdx.x * 1536;  // float4 index of first 4-p group

    float4 v0 = __ldcs(in + base4 + t);
    float4 v1 = __ldcs(in + base4 + 384 + t);
    float4 v2 = __ldcs(in + base4 + 768 + t);
    float4 v3 = __ldcs(in + base4 + 1152 + t);

    // folded init of segment tables
    if (gid < N_RAYS) { g_start[gid] = 0; g_end[gid] = 0; }
    // folded densities+colors fp32 -> fp16 pack: per-p block = 64 halves
    // [0:16) = densities, [16:64) = colors (c*3+k). Thread handles 4 floats.
    if (gid < P_CNT * 16) {
        int p = gid >> 4;
        int o = (gid & 15) * 4;                // 0,4,...,60
        float4 src = (o < 16)
            ? __ldcs(densities4 + ((size_t)p * 16 + o) / 4)
            : __ldcs(colors4    + ((size_t)p * 48 + (o - 16)) / 4);
        union { __half2 h[2]; uint2 u; } cv;
        cv.h[0] = __floats2half2_rn(src.x, src.y);
        cv.h[1] = __floats2half2_rn(src.z, src.w);
        reinterpret_cast<uint2*>(g_dc)[(size_t)p * 16 + (o >> 2)] = cv.u;
    }

    int m  = t * 4;                 // float offset within a 4-p group
    int pl = t / 96;                // local p (96 float4 per p)
    int mo = m - pl * PBLK;         // 0..383: row = mo/24 (c), col = mo%24 (a*8+d)
    int pi = mo + 2 * (mo / 24);    // padded index
    #pragma unroll
    for (int g = 0; g < 4; g++) {
        float4 v = (g == 0) ? v0 : (g == 1) ? v1 : (g == 2) ? v2 : v3;
        float* s = sm + (g * 4 + pl) * PPAD;
        s[pi + 0] = v.x; s[pi + 1] = v.y; s[pi + 2] = v.z; s[pi + 3] = v.w;
    }
    __syncthreads();

    int c = mo & 15, d = (mo >> 4) & 7, a = mo >> 7;
    int i0 = c * 26 + a * 8 + d;
    int oidx = pl * 96 + a * 32 + d * 4 + (c >> 2);
    uint2* outp = reinterpret_cast<uint2*>(g_trivecsH);
    #pragma unroll
    for (int g = 0; g < 4; g++) {
        const float* rsm = sm + (g * 4 + pl) * PPAD;
        union { __half2 h[2]; uint2 u; } ov;
        ov.h[0] = __floats2half2_rn(rsm[i0],      rsm[i0 + 26]);
        ov.h[1] = __floats2half2_rn(rsm[i0 + 52], rsm[i0 + 78]);
        outp[base4 + g * 384 + oidx] = ov.u;
    }
}

// ---------------------------------------------------------------------------
// Kernel 2: per-sample feature/sigma/color (+ segment boundaries).
// 2 threads per sample, 8 channels each via 16B gathers; pair shuffle-reduce.
// ---------------------------------------------------------------------------
__global__ __launch_bounds__(256) void sample_k(
    const float* __restrict__ gws,         // (N, 3)
    const float* __restrict__ gwl,         // (N, 3)
    const int*   __restrict__ gis,         // (N, 3)
    const int*   __restrict__ gil,         // (N, 3)
    const int*   __restrict__ tfid,        // (N,)
    const int*   __restrict__ ray_id)      // (N,) sorted
{
    int t = blockIdx.x * blockDim.x + threadIdx.x;
    int n = t >> 1;
    if (n >= N_SAMPLES) return;
    int q = t & 1;

    int p = __ldcs(tfid + n);
    const __half* base = g_trivecsH + (size_t)p * PBLK + q * 8;

    float f[8];
    #pragma unroll
    for (int i = 0; i < 8; i++) f[i] = 1.f;

    #pragma unroll
    for (int a = 0; a < 3; a++) {
        int   is = __ldcs(gis + n * 3 + a);
        int   il = __ldcs(gil + n * 3 + a);
        float ws = __ldcs(gws + n * 3 + a);
        float wl = __ldcs(gwl + n * 3 + a);
        uint4 rs = *reinterpret_cast<const uint4*>(base + a * 128 + is * 16);
        uint4 rl = *reinterpret_cast<const uint4*>(base + a * 128 + il * 16);
        const __half2* hs = reinterpret_cast<const __half2*>(&rs);
        const __half2* hl = reinterpret_cast<const __half2*>(&rl);
        #pragma unroll
        for (int i = 0; i < 4; i++) {
            float2 vs = __half22float2(hs[i]);
            float2 vl = __half22float2(hl[i]);
            f[i * 2 + 0] *= vs.x * ws + vl.x * wl;
            f[i * 2 + 1] *= vs.y * ws + vl.y * wl;
        }
    }

    // densities: halves [q*8, q*8+8) of p's 64-half block
    const __half* dch = g_dc + (size_t)p * 64;
    uint4 du = *reinterpret_cast<const uint4*>(dch + q * 8);
    const __half2* dh = reinterpret_cast<const __half2*>(&du);
    float sig = 0.f;
    #pragma unroll
    for (int i = 0; i < 4; i++) {
        float2 dv = __half22float2(dh[i]);
        sig += f[i * 2 + 0] * dv.x + f[i * 2 + 1] * dv.y;
    }

    // colors: halves [16 + q*24, 16 + q*24 + 24); element (c_local,k) at c_local*3+k
    const __half* cbh = dch + 16 + q * 24;
    uint4 cu0 = *reinterpret_cast<const uint4*>(cbh);
    uint4 cu1 = *reinterpret_cast<const uint4*>(cbh + 8);
    uint4 cu2 = *reinterpret_cast<const uint4*>(cbh + 16);
    float col[24];
    {
        const __half2* ch = reinterpret_cast<const __half2*>(&cu0);
        #pragma unroll
        for (int i = 0; i < 4; i++) { float2 v = __half22float2(ch[i]); col[i*2] = v.x; col[i*2+1] = v.y; }
        ch = reinterpret_cast<const __half2*>(&cu1);
        #pragma unroll
        for (int i = 0; i < 4; i++) { float2 v = __half22float2(ch[i]); col[8+i*2] = v.x; col[8+i*2+1] = v.y; }
        ch = reinterpret_cast<const __half2*>(&cu2);
        #pragma unroll
        for (int i = 0; i < 4; i++) { float2 v = __half22float2(ch[i]); col[16+i*2] = v.x; col[16+i*2+1] = v.y; }
    }
    float cr = 0.f, cg = 0.f, cbv = 0.f;
    #pragma unroll
    for (int c = 0; c < 8; c++) {
        cr  += f[c] * col[c * 3 + 0];
        cg  += f[c] * col[c * 3 + 1];
        cbv += f[c] * col[c * 3 + 2];
    }

    // pair reduction
    sig += __shfl_xor_sync(0xffffffffu, sig, 1);
    cr  += __shfl_xor_sync(0xffffffffu, cr,  1);
    cg  += __shfl_xor_sync(0xffffffffu, cg,  1);
    cbv += __shfl_xor_sync(0xffffffffu, cbv, 1);

    if (q == 0) {
        // DENSITY_SHIFT = 0, DENSITY_SCALE = 1
        float density = (sig > 15.f) ? sig : log1pf(__expf(sig));
        float alpha = 1.f - __expf(-density * STEP_SIZE);
        float rr = 1.f / (1.f + __expf(-cr));
        float rg = 1.f / (1.f + __expf(-cg));
        float rb = 1.f / (1.f + __expf(-cbv));
        g_samp[n] = make_float4(alpha, rr, rg, rb);
    } else {
        int r = __ldcs(ray_id + n);
        int rp = (n > 0) ? __ldcs(ray_id + n - 1) : -1;
        int rn = (n < N_SAMPLES - 1) ? __ldcs(ray_id + n + 1) : -1;
        if (rp != r) g_start[r] = n;
        if (rn != r) g_end[r]   = n + 1;
    }
}

// ---------------------------------------------------------------------------
// Kernel 3: per-ray composite. Multiplicative transmittance, 1-deep prefetch.
// ---------------------------------------------------------------------------
__global__ __launch_bounds__(256) void ray_k(
    const int*   __restrict__ step_id,
    const float* __restrict__ t_min,
    const float* __restrict__ bg,
    float*       __restrict__ out)
{
    int r = blockIdx.x * blockDim.x + threadIdx.x;
    if (r >= N_RAYS) return;

    int s = g_start[r];
    int e = g_end[r];
    float tm = t_min[r];

    float T = 1.f;
    float ra = 0.f, ga = 0.f, ba = 0.f, da = 0.f;
    float4 sp; int st = 0;
    if (s < e) { sp = __ldcs(g_samp + s); st = __ldcs(step_id + s); }
    for (int j = s; j < e; j++) {
        float4 cur = sp;
        int    cst = st;
        if (j + 1 < e) { sp = __ldcs(g_samp + j + 1); st = __ldcs(step_id + j + 1); }
        float w = cur.x * T;
        ra += w * cur.y;
        ga += w * cur.z;
        ba += w * cur.w;
        da += w * (tm + (float)cst * STEP_SIZE);
        T *= (1.f - cur.x);
    }
    out[0 * N_RAYS + r] = ra + T * __ldg(bg + 0);
    out[1 * N_RAYS + r] = ga + T * __ldg(bg + 1);
    out[2 * N_RAYS + r] = ba + T * __ldg(bg + 2);
    out[3 * N_RAYS + r] = da;          // depth map
    out[4 * N_RAYS + r] = 1.f - T;     // alpha map
}

extern "C" void kernel_launch(void* const* d_in, const int* in_sizes, int n_in,
                              void* d_out, int out_size) {
    const float* trivecs   = (const float*)d_in[0];
    const float* densities = (const float*)d_in[1];
    const float* colors    = (const float*)d_in[2];
    const float* gws       = (const float*)d_in[3];
    const float* gwl       = (const float*)d_in[4];
    const float* t_min     = (const float*)d_in[5];
    const float* bg        = (const float*)d_in[6];
    const int*   gis       = (const int*)d_in[7];
    const int*   gil       = (const int*)d_in[8];
    const int*   tfid      = (const int*)d_in[9];
    const int*   ray_id    = (const int*)d_in[10];
    const int*   step_id   = (const int*)d_in[11];
    float* out = (float*)d_out;

    transpose_k<<<P_CNT / 16, 384>>>((const float4*)trivecs,
                                     (const float4*)densities,
                                     (const float4*)colors);
    sample_k<<<(2 * N_SAMPLES + 255) / 256, 256>>>(gws, gwl, gis, gil, tfid, ray_id);
    ray_k<<<(N_RAYS + 255) / 256, 256>>>(step_id, t_min, bg, out);
}